// round 1
// baseline (speedup 1.0000x reference)
#include <cuda_runtime.h>
#include <math.h>

// Problem constants (match reference)
#define BB 512
#define TT 128
#define DD 512
#define KK 256          // DD/2 rotation blocks
#define ALPHA 0.1f
#define EPSN 1e-5f

// Kernel config
#define GCTA 128        // CTAs (one per SM-ish; L2-traffic/FFMA balance point)
#define MPER 4          // batch elements per CTA  (GCTA*MPER == BB)
#define NT 256          // threads per CTA: thread k owns 2x2 block k

#define AROWS 96        // rows of A cached in dynamic smem (96*512*4 = 192KB)

__global__ void __launch_bounds__(NT, 1)
can_path_kernel(const float* __restrict__ dx_pi,   // [B,T,2]
                const float* __restrict__ z0,      // [B,D]
                const float* __restrict__ x0,      // [B,2]
                const float* __restrict__ omega,   // [K,2]
                const float* __restrict__ Ag,      // [D,D] (exactly symmetric)
                const float* __restrict__ z0b,     // [D]
                float* __restrict__ out_z,         // [B,T,D]
                float* __restrict__ out_x)         // [B,T,2]
{
    extern __shared__ __align__(16) float As[];    // AROWS * DD floats

    __shared__ __align__(16) float zx_s[MPER][DD]; // z(x) for the M batch rows
    __shared__ float x_s[MPER][2];
    __shared__ float red_s[8][8];
    __shared__ float dxt_s[8];
    __shared__ float scale_s;

    const int k    = threadIdx.x;          // block index 0..255
    const int lane = k & 31;
    const int wid  = k >> 5;
    const int base = blockIdx.x * MPER;    // first batch element of this CTA

    // ---- preload A[0:AROWS] into smem (vectorized) ----
    {
        const float4* src = (const float4*)Ag;
        float4* dst = (float4*)As;
        const int n4 = AROWS * DD / 4;
        for (int i = k; i < n4; i += NT) dst[i] = src[i];
    }

    // ---- per-thread constants ----
    const float om0 = omega[2 * k];
    const float om1 = omega[2 * k + 1];
    const float a0  = z0b[2 * k];
    const float a1  = z0b[2 * k + 1];

    // norm of z0_base (rotation-invariant => reference's per-x norm equals this)
    {
        float v = a0 * a0 + a1 * a1;
        #pragma unroll
        for (int o = 16; o; o >>= 1) v += __shfl_xor_sync(0xFFFFFFFFu, v, o);
        if (lane == 0) red_s[wid][0] = v;
    }
    if (k < MPER * 2) x_s[k >> 1][k & 1] = x0[(base + (k >> 1)) * 2 + (k & 1)];
    __syncthreads();
    if (k == 0) {
        float s = 0.f;
        #pragma unroll
        for (int w = 0; w < 8; w++) s += red_s[w][0];
        scale_s = 1.0f / (sqrtf(s) + EPSN);
    }
    __syncthreads();

    const float p0 = a0 * scale_s;   // pre-normalized base latent block
    const float p1 = a1 * scale_s;

    // carried z: thread k holds block k of each of its M batch rows
    float zc[MPER][2];
    #pragma unroll
    for (int m = 0; m < MPER; m++) {
        zc[m][0] = z0[(base + m) * DD + 2 * k];
        zc[m][1] = z0[(base + m) * DD + 2 * k + 1];
    }

    const float2* A2  = (const float2*)Ag;  // [DD][KK] float2 view
    const float2* As2 = (const float2*)As;

    for (int t = 0; t < TT; t++) {
        // ---- phase 1: z(x) = T(x) z0_base / n  for each m ----
        float zxr[MPER][2];
        #pragma unroll
        for (int m = 0; m < MPER; m++) {
            float th = fmaf(om0, x_s[m][0], om1 * x_s[m][1]);
            float s, c;
            sincosf(th, &s, &c);
            float u0 = c * p0 - s * p1;
            float u1 = s * p0 + c * p1;
            zxr[m][0] = u0; zxr[m][1] = u1;
            zx_s[m][2 * k]     = u0;
            zx_s[m][2 * k + 1] = u1;
        }
        __syncthreads();

        // ---- phase 2: w = zx @ A  (thread k computes columns 2k,2k+1) ----
        float acc[MPER][2];
        #pragma unroll
        for (int m = 0; m < MPER; m++) { acc[m][0] = 0.f; acc[m][1] = 0.f; }

        // smem-cached rows
        #pragma unroll 2
        for (int i = 0; i < AROWS; i += 4) {
            float2 b0 = As2[(i + 0) * KK + k];
            float2 b1 = As2[(i + 1) * KK + k];
            float2 b2 = As2[(i + 2) * KK + k];
            float2 b3 = As2[(i + 3) * KK + k];
            #pragma unroll
            for (int m = 0; m < MPER; m++) {
                float4 zv = *(const float4*)&zx_s[m][i];
                acc[m][0] = fmaf(zv.x, b0.x, acc[m][0]);
                acc[m][1] = fmaf(zv.x, b0.y, acc[m][1]);
                acc[m][0] = fmaf(zv.y, b1.x, acc[m][0]);
                acc[m][1] = fmaf(zv.y, b1.y, acc[m][1]);
                acc[m][0] = fmaf(zv.z, b2.x, acc[m][0]);
                acc[m][1] = fmaf(zv.z, b2.y, acc[m][1]);
                acc[m][0] = fmaf(zv.w, b3.x, acc[m][0]);
                acc[m][1] = fmaf(zv.w, b3.y, acc[m][1]);
            }
        }
        // L2-streamed rows
        #pragma unroll 2
        for (int i = AROWS; i < DD; i += 4) {
            float2 b0 = A2[(i + 0) * KK + k];
            float2 b1 = A2[(i + 1) * KK + k];
            float2 b2 = A2[(i + 2) * KK + k];
            float2 b3 = A2[(i + 3) * KK + k];
            #pragma unroll
            for (int m = 0; m < MPER; m++) {
                float4 zv = *(const float4*)&zx_s[m][i];
                acc[m][0] = fmaf(zv.x, b0.x, acc[m][0]);
                acc[m][1] = fmaf(zv.x, b0.y, acc[m][1]);
                acc[m][0] = fmaf(zv.y, b1.x, acc[m][0]);
                acc[m][1] = fmaf(zv.y, b1.y, acc[m][1]);
                acc[m][0] = fmaf(zv.z, b2.x, acc[m][0]);
                acc[m][1] = fmaf(zv.z, b2.y, acc[m][1]);
                acc[m][0] = fmaf(zv.w, b3.x, acc[m][0]);
                acc[m][1] = fmaf(zv.w, b3.y, acc[m][1]);
            }
        }

        // ---- phase 3: g_k, reduce dx_can = ALPHA * omega^T g ----
        float r[8];
        #pragma unroll
        for (int m = 0; m < MPER; m++) {
            float g = zxr[m][0] * acc[m][1] - zxr[m][1] * acc[m][0];
            r[2 * m]     = om0 * g;
            r[2 * m + 1] = om1 * g;
        }
        #pragma unroll
        for (int j = 0; j < 8; j++) {
            #pragma unroll
            for (int o = 16; o; o >>= 1) r[j] += __shfl_xor_sync(0xFFFFFFFFu, r[j], o);
        }
        if (lane == 0) {
            #pragma unroll
            for (int j = 0; j < 8; j++) red_s[wid][j] = r[j];
        }
        __syncthreads();
        if (k < 8) {
            float s = 0.f;
            #pragma unroll
            for (int w = 0; w < 8; w++) s += red_s[w][k];
            const int m = k >> 1, j = k & 1;
            float dxt = dx_pi[((base + m) * TT + t) * 2 + j] + ALPHA * s;
            dxt_s[k] = dxt;
            float xn = x_s[m][j] + dxt;
            xn = fminf(fmaxf(xn, 0.0f), 2.0f);   // BOX_W == BOX_H == 2
            x_s[m][j] = xn;
            out_x[((base + m) * TT + t) * 2 + j] = xn;
        }
        __syncthreads();

        // ---- phase 4: carried z' = T(dx_total) z ; write outputs ----
        #pragma unroll
        for (int m = 0; m < MPER; m++) {
            float th2 = fmaf(om0, dxt_s[2 * m], om1 * dxt_s[2 * m + 1]);
            float s2, c2;
            sincosf(th2, &s2, &c2);
            float zn0 = c2 * zc[m][0] - s2 * zc[m][1];
            float zn1 = s2 * zc[m][0] + c2 * zc[m][1];
            zc[m][0] = zn0; zc[m][1] = zn1;
            float2* op = (float2*)&out_z[((size_t)(base + m) * TT + t) * DD + 2 * k];
            *op = make_float2(zn0, zn1);
        }
        // no barrier needed: next phase-1 writes are ordered by phase-3 syncs
    }
}

extern "C" void kernel_launch(void* const* d_in, const int* in_sizes, int n_in,
                              void* d_out, int out_size) {
    (void)in_sizes; (void)n_in; (void)out_size;
    const float* dx_pi = (const float*)d_in[0];   // [512,128,2]
    const float* z0    = (const float*)d_in[1];   // [512,512]
    const float* x0    = (const float*)d_in[2];   // [512,2]
    const float* omega = (const float*)d_in[3];   // [256,2]
    const float* Ag    = (const float*)d_in[4];   // [512,512]
    const float* z0b   = (const float*)d_in[5];   // [512]

    float* out_z = (float*)d_out;                       // [512,128,512]
    float* out_x = out_z + (size_t)BB * TT * DD;        // [512,128,2]

    const size_t shmem = (size_t)AROWS * DD * sizeof(float);  // 192 KB
    cudaFuncSetAttribute(can_path_kernel,
                         cudaFuncAttributeMaxDynamicSharedMemorySize,
                         (int)shmem);
    can_path_kernel<<<GCTA, NT, shmem>>>(dx_pi, z0, x0, omega, Ag, z0b,
                                         out_z, out_x);
}